// round 1
// baseline (speedup 1.0000x reference)
#include <cuda_runtime.h>
#include <cstdint>

#define NNODES 8192
#define FEATD  1024
#define HDIM   512
#define GDIM   (5*HDIM)
#define NCTA   128
#define UPC    4                 // hidden units per CTA (HDIM / NCTA)
#define NWARPS 20                // 5 gates * UPC
#define NTHR   (NWARPS*32)

// Scratch (static __device__ arrays: allocation-free per harness rules)
__device__ float g_xgb[(size_t)NNODES * GDIM];   // Wx·x + bx + bh   [N,5H]
__device__ float g_pxb[(size_t)NNODES * HDIM];   // Wpx·x + bpx      [N,H]
__device__ float g_C[(size_t)NNODES * HDIM];     // cell states      [N,H]
__device__ unsigned int g_counter;               // global step barrier counter

__global__ void init_counter_kernel() { g_counter = 0u; }

__device__ __forceinline__ unsigned int ld_acquire_gpu(const unsigned int* p) {
    unsigned int v;
    asm volatile("ld.acquire.gpu.global.u32 %0, [%1];" : "=r"(v) : "l"(p) : "memory");
    return v;
}
__device__ __forceinline__ void red_release_add(unsigned int* p, unsigned int v) {
    asm volatile("red.release.gpu.global.add.u32 [%0], %1;" :: "l"(p), "r"(v) : "memory");
}

__device__ __forceinline__ float sigm(float x) {
    return 1.0f / (1.0f + __expf(-x));
}
__device__ __forceinline__ float tanhfast(float x) {
    // tanh(x) = 1 - 2/(e^{2x}+1); saturates cleanly at +/-1 (no NaN for |x| large)
    return 1.0f - 2.0f / (__expf(2.0f * x) + 1.0f);
}

// ---------------------------------------------------------------------------
// Batched precompute GEMM:  C[M,N] = A[M,K] * B[N,K]^T + b1[N] (+ b2[N])
// Classic 128x128x8 SMEM-tiled fp32 SGEMM, 256 threads, 8x8 per-thread tile.
// M=8192, K=1024, N in {512, 2560}; all dims divide tiles exactly.
// ---------------------------------------------------------------------------
__global__ __launch_bounds__(256) void sgemm_bt_bias(
    const float* __restrict__ A, const float* __restrict__ B,
    const float* __restrict__ b1, const float* __restrict__ b2,
    float* __restrict__ C, int M, int N, int K)
{
    const int BM = 128, BN = 128;
    __shared__ float As[8][BM + 4];
    __shared__ float Bs[8][BN + 4];

    const int tid = threadIdx.x;
    const int bxi = blockIdx.x, byi = blockIdx.y;
    const int loadRow = tid >> 1;            // 0..127
    const int loadCol = (tid & 1) << 2;      // 0 or 4

    const float* Ab = A + (size_t)byi * BM * K;
    const float* Bb = B + (size_t)bxi * BN * K;

    const int ty = tid >> 4;                 // 0..15
    const int tx = tid & 15;                 // 0..15

    float acc[8][8];
#pragma unroll
    for (int i = 0; i < 8; i++)
#pragma unroll
        for (int j = 0; j < 8; j++) acc[i][j] = 0.0f;

    for (int k0 = 0; k0 < K; k0 += 8) {
        float4 av = *(const float4*)(Ab + (size_t)loadRow * K + k0 + loadCol);
        float4 bv = *(const float4*)(Bb + (size_t)loadRow * K + k0 + loadCol);
        As[loadCol + 0][loadRow] = av.x;
        As[loadCol + 1][loadRow] = av.y;
        As[loadCol + 2][loadRow] = av.z;
        As[loadCol + 3][loadRow] = av.w;
        Bs[loadCol + 0][loadRow] = bv.x;
        Bs[loadCol + 1][loadRow] = bv.y;
        Bs[loadCol + 2][loadRow] = bv.z;
        Bs[loadCol + 3][loadRow] = bv.w;
        __syncthreads();

#pragma unroll
        for (int k = 0; k < 8; k++) {
            float ar[8], br[8];
#pragma unroll
            for (int i = 0; i < 8; i++) ar[i] = As[k][ty * 8 + i];
#pragma unroll
            for (int j = 0; j < 8; j++) br[j] = Bs[k][tx * 8 + j];
#pragma unroll
            for (int i = 0; i < 8; i++)
#pragma unroll
                for (int j = 0; j < 8; j++)
                    acc[i][j] = fmaf(ar[i], br[j], acc[i][j]);
        }
        __syncthreads();
    }

    // epilogue: add bias(es), vectorized store
#pragma unroll
    for (int i = 0; i < 8; i++) {
        int m = byi * BM + ty * 8 + i;
        int nbase = bxi * BN + tx * 8;
        float v[8];
#pragma unroll
        for (int j = 0; j < 8; j++) {
            v[j] = acc[i][j] + b1[nbase + j];
            if (b2) v[j] += b2[nbase + j];
        }
        float4* out = (float4*)(C + (size_t)m * N + nbase);
        out[0] = make_float4(v[0], v[1], v[2], v[3]);
        out[1] = make_float4(v[4], v[5], v[6], v[7]);
    }
}

// ---------------------------------------------------------------------------
// Persistent serial recurrence kernel.
// 128 CTAs x 640 threads. CTA c owns hidden units [4c, 4c+4).
// Warp w (0..19) owns Wh row (w>>2)*512 + 4c + (w&3); its 512 weights live in
// 16 registers per lane (k = 4*lane + 128*i).
// Per step: global spin barrier -> load h[parent] (L1-dedup across warps) ->
// 16 FMA + butterfly reduce -> warp0 lanes 0..3 assemble gates, update c/h,
// store coalesced, red.release arrive (+4 per CTA per step).
// ---------------------------------------------------------------------------
__global__ __launch_bounds__(NTHR, 1) void treelstm_seq_kernel(
    const float* __restrict__ Wh, const int* __restrict__ parents,
    float* __restrict__ Hout)
{
    const int cta  = blockIdx.x;
    const int tid  = threadIdx.x;
    const int w    = tid >> 5;
    const int lane = tid & 31;
    const int gate = w >> 2;          // 0:i 1:o 2:f 3:u 4:r
    const int ju   = w & 3;
    const int row  = gate * HDIM + cta * UPC + ju;   // row of Wh / xgb

    // Pin this row's weights in registers
    const float* wrow = Wh + (size_t)row * HDIM + 4 * lane;
    const float4 wv0 = *(const float4*)(wrow + 0);
    const float4 wv1 = *(const float4*)(wrow + 128);
    const float4 wv2 = *(const float4*)(wrow + 256);
    const float4 wv3 = *(const float4*)(wrow + 384);

    __shared__ float s_dots[NWARPS];

    const bool isUnitLane = (w == 0) && (lane < UPC);
    const int  myUnit = cta * UPC + lane;            // valid for unit lanes

    float xgb_next = g_xgb[row];                     // t = 0 prefetch
    float px_next  = isUnitLane ? g_pxb[myUnit] : 0.0f;
    float c_last   = 0.0f;                           // register-forwarded cell state
    unsigned int target = 0;

    for (int t = 0; t < NNODES; t++) {
        const float xgbv = xgb_next;
        const float pxv  = px_next;
        const int   p    = parents[t];

        // --- chip-wide step barrier: wait for all of step t-1 ---
        if (tid == 0) {
            while (ld_acquire_gpu(&g_counter) < target) { }
        }
        __syncthreads();
        target += UPC * NCTA;

        // --- parent cell state (register forward on chain, load otherwise) ---
        float cpar = 0.0f;
        if (isUnitLane && p >= 0) {
            cpar = (p == t - 1) ? c_last : g_C[(size_t)p * HDIM + myUnit];
        }

        // --- dot(Wh[row], h[parent]) ---
        float a0 = 0.0f, a1 = 0.0f, a2 = 0.0f, a3 = 0.0f;
        if (p >= 0) {
            const float4* hp = (const float4*)(Hout + (size_t)p * HDIM) + lane;
            float4 h0 = hp[0];
            float4 h1 = hp[32];
            float4 h2 = hp[64];
            float4 h3 = hp[96];
            a0 = fmaf(wv0.x, h0.x, fmaf(wv0.y, h0.y, fmaf(wv0.z, h0.z, wv0.w * h0.w)));
            a1 = fmaf(wv1.x, h1.x, fmaf(wv1.y, h1.y, fmaf(wv1.z, h1.z, wv1.w * h1.w)));
            a2 = fmaf(wv2.x, h2.x, fmaf(wv2.y, h2.y, fmaf(wv2.z, h2.z, wv2.w * h2.w)));
            a3 = fmaf(wv3.x, h3.x, fmaf(wv3.y, h3.y, fmaf(wv3.z, h3.z, wv3.w * h3.w)));
        }
        float acc = (a0 + a1) + (a2 + a3);
#pragma unroll
        for (int off = 16; off; off >>= 1)
            acc += __shfl_xor_sync(0xffffffffu, acc, off);
        if (lane == 0) s_dots[w] = acc + xgbv;
        __syncthreads();

        // --- gate assembly + state update (warp0 lanes 0..3) ---
        if (isUnitLane) {
            float gi = s_dots[0 * UPC + lane];
            float go = s_dots[1 * UPC + lane];
            float gf = s_dots[2 * UPC + lane];
            float gu = s_dots[3 * UPC + lane];
            float gr = s_dots[4 * UPC + lane];
            float iv = sigm(gi);
            float ov = sigm(go);
            float fv = sigm(gf);
            float uv = tanhfast(gu);
            float rv = sigm(gr);
            float c  = fmaf(fv, cpar, iv * uv);
            float hh = ov * tanhfast(c);
            float hf = rv * hh + (1.0f - rv) * pxv;
            c_last = c;
            g_C[(size_t)t * HDIM + myUnit]  = c;
            Hout[(size_t)t * HDIM + myUnit] = hf;
            red_release_add(&g_counter, 1u);          // release orders my stores
        }

        // --- prefetch static per-node data for t+1 (hidden under sync) ---
        if (t + 1 < NNODES) {
            xgb_next = g_xgb[(size_t)(t + 1) * GDIM + row];
            if (isUnitLane) px_next = g_pxb[(size_t)(t + 1) * HDIM + myUnit];
        }
    }
}

extern "C" void kernel_launch(void* const* d_in, const int* in_sizes, int n_in,
                              void* d_out, int out_size) {
    const float* features = (const float*)d_in[0];
    const int*   parents  = (const int*)d_in[1];
    const float* Wpx      = (const float*)d_in[2];
    const float* bpx      = (const float*)d_in[3];
    const float* Wx       = (const float*)d_in[4];
    const float* bx       = (const float*)d_in[5];
    const float* Wh       = (const float*)d_in[6];
    const float* bh       = (const float*)d_in[7];
    float* Hout = (float*)d_out;

    float* d_pxb = nullptr;
    float* d_xgb = nullptr;
    cudaGetSymbolAddress((void**)&d_pxb, g_pxb);
    cudaGetSymbolAddress((void**)&d_xgb, g_xgb);

    // 1) reset barrier counter (graph replays need a fresh counter each launch)
    init_counter_kernel<<<1, 1>>>();

    // 2) batched x-side projections
    dim3 gpx(HDIM / 128, NNODES / 128);
    sgemm_bt_bias<<<gpx, 256>>>(features, Wpx, bpx, nullptr, d_pxb,
                                NNODES, HDIM, FEATD);
    dim3 gxg(GDIM / 128, NNODES / 128);
    sgemm_bt_bias<<<gxg, 256>>>(features, Wx, bx, bh, d_xgb,
                                NNODES, GDIM, FEATD);

    // 3) serial recurrence (persistent, co-resident grid: 128 CTAs <= #SMs)
    treelstm_seq_kernel<<<NCTA, NTHR>>>(Wh, parents, Hout);
}

// round 2
// speedup vs baseline: 1.0035x; 1.0035x over previous
#include <cuda_runtime.h>
#include <cstdint>

#define NNODES 8192
#define FEATD  1024
#define HDIM   512
#define GDIM   (5*HDIM)
#define NCTA   128
#define UPC    4                 // hidden units per CTA (HDIM / NCTA)
#define NWARPS 20                // 5 gates * UPC
#define NTHR   (NWARPS*32)

// Scratch (static __device__ arrays: allocation-free per harness rules)
__device__ float g_xgb[(size_t)NNODES * GDIM];   // Wx·x + bx + bh   [N,5H]
__device__ float g_pxb[(size_t)NNODES * HDIM];   // Wpx·x + bpx      [N,H]
__device__ float g_C[(size_t)NNODES * HDIM];     // cell states      [N,H]
__device__ unsigned int g_counter;               // global step barrier counter

__global__ void init_counter_kernel() { g_counter = 0u; }

__device__ __forceinline__ unsigned int ld_acquire_gpu(const unsigned int* p) {
    unsigned int v;
    asm volatile("ld.acquire.gpu.global.u32 %0, [%1];" : "=r"(v) : "l"(p) : "memory");
    return v;
}
__device__ __forceinline__ void red_release_add(unsigned int* p, unsigned int v) {
    asm volatile("red.release.gpu.global.add.u32 [%0], %1;" :: "l"(p), "r"(v) : "memory");
}

__device__ __forceinline__ float sigm(float x) {
    return 1.0f / (1.0f + __expf(-x));
}
__device__ __forceinline__ float tanhfast(float x) {
    // tanh(x) = 1 - 2/(e^{2x}+1); saturates cleanly at +/-1 (no NaN for |x| large)
    return 1.0f - 2.0f / (__expf(2.0f * x) + 1.0f);
}

// ---------------------------------------------------------------------------
// Batched precompute GEMM:  C[M,N] = A[M,K] * B[N,K]^T + b1[N] (+ b2[N])
// Classic 128x128x8 SMEM-tiled fp32 SGEMM, 256 threads, 8x8 per-thread tile.
// M=8192, K=1024, N in {512, 2560}; all dims divide tiles exactly.
// ---------------------------------------------------------------------------
__global__ __launch_bounds__(256) void sgemm_bt_bias(
    const float* __restrict__ A, const float* __restrict__ B,
    const float* __restrict__ b1, const float* __restrict__ b2,
    float* __restrict__ C, int M, int N, int K)
{
    const int BM = 128, BN = 128;
    __shared__ float As[8][BM + 4];
    __shared__ float Bs[8][BN + 4];

    const int tid = threadIdx.x;
    const int bxi = blockIdx.x, byi = blockIdx.y;
    const int loadRow = tid >> 1;            // 0..127
    const int loadCol = (tid & 1) << 2;      // 0 or 4

    const float* Ab = A + (size_t)byi * BM * K;
    const float* Bb = B + (size_t)bxi * BN * K;

    const int ty = tid >> 4;                 // 0..15
    const int tx = tid & 15;                 // 0..15

    float acc[8][8];
#pragma unroll
    for (int i = 0; i < 8; i++)
#pragma unroll
        for (int j = 0; j < 8; j++) acc[i][j] = 0.0f;

    for (int k0 = 0; k0 < K; k0 += 8) {
        float4 av = *(const float4*)(Ab + (size_t)loadRow * K + k0 + loadCol);
        float4 bv = *(const float4*)(Bb + (size_t)loadRow * K + k0 + loadCol);
        As[loadCol + 0][loadRow] = av.x;
        As[loadCol + 1][loadRow] = av.y;
        As[loadCol + 2][loadRow] = av.z;
        As[loadCol + 3][loadRow] = av.w;
        Bs[loadCol + 0][loadRow] = bv.x;
        Bs[loadCol + 1][loadRow] = bv.y;
        Bs[loadCol + 2][loadRow] = bv.z;
        Bs[loadCol + 3][loadRow] = bv.w;
        __syncthreads();

#pragma unroll
        for (int k = 0; k < 8; k++) {
            float ar[8], br[8];
#pragma unroll
            for (int i = 0; i < 8; i++) ar[i] = As[k][ty * 8 + i];
#pragma unroll
            for (int j = 0; j < 8; j++) br[j] = Bs[k][tx * 8 + j];
#pragma unroll
            for (int i = 0; i < 8; i++)
#pragma unroll
                for (int j = 0; j < 8; j++)
                    acc[i][j] = fmaf(ar[i], br[j], acc[i][j]);
        }
        __syncthreads();
    }

    // epilogue: add bias(es), vectorized store
#pragma unroll
    for (int i = 0; i < 8; i++) {
        int m = byi * BM + ty * 8 + i;
        int nbase = bxi * BN + tx * 8;
        float v[8];
#pragma unroll
        for (int j = 0; j < 8; j++) {
            v[j] = acc[i][j] + b1[nbase + j];
            if (b2) v[j] += b2[nbase + j];
        }
        float4* out = (float4*)(C + (size_t)m * N + nbase);
        out[0] = make_float4(v[0], v[1], v[2], v[3]);
        out[1] = make_float4(v[4], v[5], v[6], v[7]);
    }
}

// ---------------------------------------------------------------------------
// Persistent serial recurrence kernel.
// 128 CTAs x 640 threads. CTA c owns hidden units [4c, 4c+4).
// Warp w (0..19) owns Wh row (w>>2)*512 + 4c + (w&3); its 512 weights live in
// 16 registers per lane (k = 4*lane + 128*i).
// Per step: global spin barrier -> load h[parent] (L1-dedup across warps) ->
// 16 FMA + butterfly reduce -> warp0 lanes 0..3 assemble gates, update c/h,
// store coalesced, red.release arrive (+4 per CTA per step).
// ---------------------------------------------------------------------------
__global__ __launch_bounds__(NTHR, 1) void treelstm_seq_kernel(
    const float* __restrict__ Wh, const int* __restrict__ parents,
    float* __restrict__ Hout)
{
    const int cta  = blockIdx.x;
    const int tid  = threadIdx.x;
    const int w    = tid >> 5;
    const int lane = tid & 31;
    const int gate = w >> 2;          // 0:i 1:o 2:f 3:u 4:r
    const int ju   = w & 3;
    const int row  = gate * HDIM + cta * UPC + ju;   // row of Wh / xgb

    // Pin this row's weights in registers
    const float* wrow = Wh + (size_t)row * HDIM + 4 * lane;
    const float4 wv0 = *(const float4*)(wrow + 0);
    const float4 wv1 = *(const float4*)(wrow + 128);
    const float4 wv2 = *(const float4*)(wrow + 256);
    const float4 wv3 = *(const float4*)(wrow + 384);

    __shared__ float s_dots[NWARPS];

    const bool isUnitLane = (w == 0) && (lane < UPC);
    const int  myUnit = cta * UPC + lane;            // valid for unit lanes

    float xgb_next = g_xgb[row];                     // t = 0 prefetch
    float px_next  = isUnitLane ? g_pxb[myUnit] : 0.0f;
    float c_last   = 0.0f;                           // register-forwarded cell state
    unsigned int target = 0;

    for (int t = 0; t < NNODES; t++) {
        const float xgbv = xgb_next;
        const float pxv  = px_next;
        const int   p    = parents[t];

        // --- chip-wide step barrier: wait for all of step t-1 ---
        if (tid == 0) {
            while (ld_acquire_gpu(&g_counter) < target) { }
        }
        __syncthreads();
        target += UPC * NCTA;

        // --- parent cell state (register forward on chain, load otherwise) ---
        float cpar = 0.0f;
        if (isUnitLane && p >= 0) {
            cpar = (p == t - 1) ? c_last : g_C[(size_t)p * HDIM + myUnit];
        }

        // --- dot(Wh[row], h[parent]) ---
        float a0 = 0.0f, a1 = 0.0f, a2 = 0.0f, a3 = 0.0f;
        if (p >= 0) {
            const float4* hp = (const float4*)(Hout + (size_t)p * HDIM) + lane;
            float4 h0 = hp[0];
            float4 h1 = hp[32];
            float4 h2 = hp[64];
            float4 h3 = hp[96];
            a0 = fmaf(wv0.x, h0.x, fmaf(wv0.y, h0.y, fmaf(wv0.z, h0.z, wv0.w * h0.w)));
            a1 = fmaf(wv1.x, h1.x, fmaf(wv1.y, h1.y, fmaf(wv1.z, h1.z, wv1.w * h1.w)));
            a2 = fmaf(wv2.x, h2.x, fmaf(wv2.y, h2.y, fmaf(wv2.z, h2.z, wv2.w * h2.w)));
            a3 = fmaf(wv3.x, h3.x, fmaf(wv3.y, h3.y, fmaf(wv3.z, h3.z, wv3.w * h3.w)));
        }
        float acc = (a0 + a1) + (a2 + a3);
#pragma unroll
        for (int off = 16; off; off >>= 1)
            acc += __shfl_xor_sync(0xffffffffu, acc, off);
        if (lane == 0) s_dots[w] = acc + xgbv;
        __syncthreads();

        // --- gate assembly + state update (warp0 lanes 0..3) ---
        if (isUnitLane) {
            float gi = s_dots[0 * UPC + lane];
            float go = s_dots[1 * UPC + lane];
            float gf = s_dots[2 * UPC + lane];
            float gu = s_dots[3 * UPC + lane];
            float gr = s_dots[4 * UPC + lane];
            float iv = sigm(gi);
            float ov = sigm(go);
            float fv = sigm(gf);
            float uv = tanhfast(gu);
            float rv = sigm(gr);
            float c  = fmaf(fv, cpar, iv * uv);
            float hh = ov * tanhfast(c);
            float hf = rv * hh + (1.0f - rv) * pxv;
            c_last = c;
            g_C[(size_t)t * HDIM + myUnit]  = c;
            Hout[(size_t)t * HDIM + myUnit] = hf;
            red_release_add(&g_counter, 1u);          // release orders my stores
        }

        // --- prefetch static per-node data for t+1 (hidden under sync) ---
        if (t + 1 < NNODES) {
            xgb_next = g_xgb[(size_t)(t + 1) * GDIM + row];
            if (isUnitLane) px_next = g_pxb[(size_t)(t + 1) * HDIM + myUnit];
        }
    }
}

extern "C" void kernel_launch(void* const* d_in, const int* in_sizes, int n_in,
                              void* d_out, int out_size) {
    const float* features = (const float*)d_in[0];
    const int*   parents  = (const int*)d_in[1];
    const float* Wpx      = (const float*)d_in[2];
    const float* bpx      = (const float*)d_in[3];
    const float* Wx       = (const float*)d_in[4];
    const float* bx       = (const float*)d_in[5];
    const float* Wh       = (const float*)d_in[6];
    const float* bh       = (const float*)d_in[7];
    float* Hout = (float*)d_out;

    float* d_pxb = nullptr;
    float* d_xgb = nullptr;
    cudaGetSymbolAddress((void**)&d_pxb, g_pxb);
    cudaGetSymbolAddress((void**)&d_xgb, g_xgb);

    // 1) reset barrier counter (graph replays need a fresh counter each launch)
    init_counter_kernel<<<1, 1>>>();

    // 2) batched x-side projections
    dim3 gpx(HDIM / 128, NNODES / 128);
    sgemm_bt_bias<<<gpx, 256>>>(features, Wpx, bpx, nullptr, d_pxb,
                                NNODES, HDIM, FEATD);
    dim3 gxg(GDIM / 128, NNODES / 128);
    sgemm_bt_bias<<<gxg, 256>>>(features, Wx, bx, bh, d_xgb,
                                NNODES, GDIM, FEATD);

    // 3) serial recurrence (persistent, co-resident grid: 128 CTAs <= #SMs)
    treelstm_seq_kernel<<<NCTA, NTHR>>>(Wh, parents, Hout);
}

// round 3
// speedup vs baseline: 1.0377x; 1.0341x over previous
#include <cuda_runtime.h>
#include <cstdint>

#define NNODES 8192
#define FEATD  1024
#define HDIM   512
#define GDIM   (5*HDIM)
#define NCTA   128
#define UPC    4                 // hidden units per CTA (HDIM / NCTA)
#define NWARPS 20                // 5 gates * UPC
#define NTHR   (NWARPS*32)

// Scratch (static __device__ arrays: allocation-free per harness rules)
__device__ float g_xgb[(size_t)NNODES * GDIM];   // Wx·x + bx + bh   [N,5H]
__device__ float g_pxb[(size_t)NNODES * HDIM];   // Wpx·x + bpx      [N,H]
__device__ float g_C[(size_t)NNODES * HDIM];     // cell states      [N,H]
__device__ unsigned int g_counter;               // global step barrier counter

__global__ void init_counter_kernel() { g_counter = 0u; }

__device__ __forceinline__ unsigned int ld_acquire_gpu(const unsigned int* p) {
    unsigned int v;
    asm volatile("ld.acquire.gpu.global.u32 %0, [%1];" : "=r"(v) : "l"(p) : "memory");
    return v;
}
__device__ __forceinline__ void red_release_add(unsigned int* p, unsigned int v) {
    asm volatile("red.release.gpu.global.add.u32 [%0], %1;" :: "l"(p), "r"(v) : "memory");
}

__device__ __forceinline__ float sigm(float x) {
    return 1.0f / (1.0f + __expf(-x));
}
__device__ __forceinline__ float tanhfast(float x) {
    // tanh(x) = 1 - 2/(e^{2x}+1); saturates cleanly at +/-1 (no NaN for |x| large)
    return 1.0f - 2.0f / (__expf(2.0f * x) + 1.0f);
}

// ---------------------------------------------------------------------------
// Batched precompute GEMM:  C[M,N] = A[M,K] * B[N,K]^T + b1[N] (+ b2[N])
// Classic 128x128x8 SMEM-tiled fp32 SGEMM, 256 threads, 8x8 per-thread tile.
// M=8192, K=1024, N in {512, 2560}; all dims divide tiles exactly.
// ---------------------------------------------------------------------------
__global__ __launch_bounds__(256) void sgemm_bt_bias(
    const float* __restrict__ A, const float* __restrict__ B,
    const float* __restrict__ b1, const float* __restrict__ b2,
    float* __restrict__ C, int M, int N, int K)
{
    const int BM = 128, BN = 128;
    __shared__ float As[8][BM + 4];
    __shared__ float Bs[8][BN + 4];

    const int tid = threadIdx.x;
    const int bxi = blockIdx.x, byi = blockIdx.y;
    const int loadRow = tid >> 1;            // 0..127
    const int loadCol = (tid & 1) << 2;      // 0 or 4

    const float* Ab = A + (size_t)byi * BM * K;
    const float* Bb = B + (size_t)bxi * BN * K;

    const int ty = tid >> 4;                 // 0..15
    const int tx = tid & 15;                 // 0..15

    float acc[8][8];
#pragma unroll
    for (int i = 0; i < 8; i++)
#pragma unroll
        for (int j = 0; j < 8; j++) acc[i][j] = 0.0f;

    for (int k0 = 0; k0 < K; k0 += 8) {
        float4 av = *(const float4*)(Ab + (size_t)loadRow * K + k0 + loadCol);
        float4 bv = *(const float4*)(Bb + (size_t)loadRow * K + k0 + loadCol);
        As[loadCol + 0][loadRow] = av.x;
        As[loadCol + 1][loadRow] = av.y;
        As[loadCol + 2][loadRow] = av.z;
        As[loadCol + 3][loadRow] = av.w;
        Bs[loadCol + 0][loadRow] = bv.x;
        Bs[loadCol + 1][loadRow] = bv.y;
        Bs[loadCol + 2][loadRow] = bv.z;
        Bs[loadCol + 3][loadRow] = bv.w;
        __syncthreads();

#pragma unroll
        for (int k = 0; k < 8; k++) {
            float ar[8], br[8];
#pragma unroll
            for (int i = 0; i < 8; i++) ar[i] = As[k][ty * 8 + i];
#pragma unroll
            for (int j = 0; j < 8; j++) br[j] = Bs[k][tx * 8 + j];
#pragma unroll
            for (int i = 0; i < 8; i++)
#pragma unroll
                for (int j = 0; j < 8; j++)
                    acc[i][j] = fmaf(ar[i], br[j], acc[i][j]);
        }
        __syncthreads();
    }

    // epilogue: add bias(es), vectorized store
#pragma unroll
    for (int i = 0; i < 8; i++) {
        int m = byi * BM + ty * 8 + i;
        int nbase = bxi * BN + tx * 8;
        float v[8];
#pragma unroll
        for (int j = 0; j < 8; j++) {
            v[j] = acc[i][j] + b1[nbase + j];
            if (b2) v[j] += b2[nbase + j];
        }
        float4* out = (float4*)(C + (size_t)m * N + nbase);
        out[0] = make_float4(v[0], v[1], v[2], v[3]);
        out[1] = make_float4(v[4], v[5], v[6], v[7]);
    }
}

// ---------------------------------------------------------------------------
// Persistent serial recurrence kernel.
// 128 CTAs x 640 threads. CTA c owns hidden units [4c, 4c+4).
// Warp w (0..19) owns Wh row (w>>2)*512 + 4c + (w&3); its 512 weights live in
// 16 registers per lane (k = 4*lane + 128*i).
// Per step: global spin barrier -> load h[parent] (L1-dedup across warps) ->
// 16 FMA + butterfly reduce -> warp0 lanes 0..3 assemble gates, update c/h,
// store coalesced, red.release arrive (+4 per CTA per step).
// ---------------------------------------------------------------------------
__global__ __launch_bounds__(NTHR, 1) void treelstm_seq_kernel(
    const float* __restrict__ Wh, const int* __restrict__ parents,
    float* __restrict__ Hout)
{
    const int cta  = blockIdx.x;
    const int tid  = threadIdx.x;
    const int w    = tid >> 5;
    const int lane = tid & 31;
    const int gate = w >> 2;          // 0:i 1:o 2:f 3:u 4:r
    const int ju   = w & 3;
    const int row  = gate * HDIM + cta * UPC + ju;   // row of Wh / xgb

    // Pin this row's weights in registers
    const float* wrow = Wh + (size_t)row * HDIM + 4 * lane;
    const float4 wv0 = *(const float4*)(wrow + 0);
    const float4 wv1 = *(const float4*)(wrow + 128);
    const float4 wv2 = *(const float4*)(wrow + 256);
    const float4 wv3 = *(const float4*)(wrow + 384);

    __shared__ float s_dots[NWARPS];

    const bool isUnitLane = (w == 0) && (lane < UPC);
    const int  myUnit = cta * UPC + lane;            // valid for unit lanes

    float xgb_next = g_xgb[row];                     // t = 0 prefetch
    float px_next  = isUnitLane ? g_pxb[myUnit] : 0.0f;
    float c_last   = 0.0f;                           // register-forwarded cell state
    unsigned int target = 0;

    for (int t = 0; t < NNODES; t++) {
        const float xgbv = xgb_next;
        const float pxv  = px_next;
        const int   p    = parents[t];

        // --- chip-wide step barrier: wait for all of step t-1 ---
        if (tid == 0) {
            while (ld_acquire_gpu(&g_counter) < target) { }
        }
        __syncthreads();
        target += UPC * NCTA;

        // --- parent cell state (register forward on chain, load otherwise) ---
        float cpar = 0.0f;
        if (isUnitLane && p >= 0) {
            cpar = (p == t - 1) ? c_last : g_C[(size_t)p * HDIM + myUnit];
        }

        // --- dot(Wh[row], h[parent]) ---
        float a0 = 0.0f, a1 = 0.0f, a2 = 0.0f, a3 = 0.0f;
        if (p >= 0) {
            const float4* hp = (const float4*)(Hout + (size_t)p * HDIM) + lane;
            float4 h0 = hp[0];
            float4 h1 = hp[32];
            float4 h2 = hp[64];
            float4 h3 = hp[96];
            a0 = fmaf(wv0.x, h0.x, fmaf(wv0.y, h0.y, fmaf(wv0.z, h0.z, wv0.w * h0.w)));
            a1 = fmaf(wv1.x, h1.x, fmaf(wv1.y, h1.y, fmaf(wv1.z, h1.z, wv1.w * h1.w)));
            a2 = fmaf(wv2.x, h2.x, fmaf(wv2.y, h2.y, fmaf(wv2.z, h2.z, wv2.w * h2.w)));
            a3 = fmaf(wv3.x, h3.x, fmaf(wv3.y, h3.y, fmaf(wv3.z, h3.z, wv3.w * h3.w)));
        }
        float acc = (a0 + a1) + (a2 + a3);
#pragma unroll
        for (int off = 16; off; off >>= 1)
            acc += __shfl_xor_sync(0xffffffffu, acc, off);
        if (lane == 0) s_dots[w] = acc + xgbv;
        __syncthreads();

        // --- gate assembly + state update (warp0 lanes 0..3) ---
        if (isUnitLane) {
            float gi = s_dots[0 * UPC + lane];
            float go = s_dots[1 * UPC + lane];
            float gf = s_dots[2 * UPC + lane];
            float gu = s_dots[3 * UPC + lane];
            float gr = s_dots[4 * UPC + lane];
            float iv = sigm(gi);
            float ov = sigm(go);
            float fv = sigm(gf);
            float uv = tanhfast(gu);
            float rv = sigm(gr);
            float c  = fmaf(fv, cpar, iv * uv);
            float hh = ov * tanhfast(c);
            float hf = rv * hh + (1.0f - rv) * pxv;
            c_last = c;
            g_C[(size_t)t * HDIM + myUnit]  = c;
            Hout[(size_t)t * HDIM + myUnit] = hf;
            red_release_add(&g_counter, 1u);          // release orders my stores
        }

        // --- prefetch static per-node data for t+1 (hidden under sync) ---
        if (t + 1 < NNODES) {
            xgb_next = g_xgb[(size_t)(t + 1) * GDIM + row];
            if (isUnitLane) px_next = g_pxb[(size_t)(t + 1) * HDIM + myUnit];
        }
    }
}

extern "C" void kernel_launch(void* const* d_in, const int* in_sizes, int n_in,
                              void* d_out, int out_size) {
    const float* features = (const float*)d_in[0];
    const int*   parents  = (const int*)d_in[1];
    const float* Wpx      = (const float*)d_in[2];
    const float* bpx      = (const float*)d_in[3];
    const float* Wx       = (const float*)d_in[4];
    const float* bx       = (const float*)d_in[5];
    const float* Wh       = (const float*)d_in[6];
    const float* bh       = (const float*)d_in[7];
    float* Hout = (float*)d_out;

    float* d_pxb = nullptr;
    float* d_xgb = nullptr;
    cudaGetSymbolAddress((void**)&d_pxb, g_pxb);
    cudaGetSymbolAddress((void**)&d_xgb, g_xgb);

    // 1) reset barrier counter (graph replays need a fresh counter each launch)
    init_counter_kernel<<<1, 1>>>();

    // 2) batched x-side projections
    dim3 gpx(HDIM / 128, NNODES / 128);
    sgemm_bt_bias<<<gpx, 256>>>(features, Wpx, bpx, nullptr, d_pxb,
                                NNODES, HDIM, FEATD);
    dim3 gxg(GDIM / 128, NNODES / 128);
    sgemm_bt_bias<<<gxg, 256>>>(features, Wx, bx, bh, d_xgb,
                                NNODES, GDIM, FEATD);

    // 3) serial recurrence (persistent, co-resident grid: 128 CTAs <= #SMs)
    treelstm_seq_kernel<<<NCTA, NTHR>>>(Wh, parents, Hout);
}